// round 14
// baseline (speedup 1.0000x reference)
#include <cuda_runtime.h>
#include <cuda_fp16.h>
#include <cstdint>

#define NN      16384
#define DIMF    64
#define GRIDX   296                   // 2 CTAs x 148 SMs, balanced
#define KC      64                    // K elements per pipeline chunk
#define NC      (NN / KC)             // 256 chunks
#define THREADS 128
#define STAGES  3
#define W_STAGE 8192                  // per warp per stage: 4KB A quadrant + 4KB B half
#define W_BYTES (STAGES * W_STAGE)    // 24576 per warp
#define DYN_SMEM (4 * W_BYTES)        // 98304

// transposed x in fp16: g_xT[d][j] = (half)x[j][d]
__device__ __half g_xT[DIMF * NN];

// ---------------- helpers ----------------
__device__ __forceinline__ uint32_t smem_u32(const void* p) {
    uint32_t a;
    asm("{ .reg .u64 t; cvta.to.shared.u64 t, %1; cvt.u32.u64 %0, t; }"
        : "=r"(a) : "l"(p));
    return a;
}

__device__ __forceinline__ void ldmx4(uint32_t r[4], uint32_t addr) {
    asm volatile("ldmatrix.sync.aligned.m8n8.x4.shared.b16 {%0,%1,%2,%3}, [%4];"
                 : "=r"(r[0]), "=r"(r[1]), "=r"(r[2]), "=r"(r[3]) : "r"(addr));
}

__device__ __forceinline__ void mma16816(float* c, const uint32_t a[4],
                                         uint32_t b0, uint32_t b1) {
    asm volatile(
        "mma.sync.aligned.m16n8k16.row.col.f32.f16.f16.f32 "
        "{%0,%1,%2,%3}, {%4,%5,%6,%7}, {%8,%9}, {%0,%1,%2,%3};"
        : "+f"(c[0]), "+f"(c[1]), "+f"(c[2]), "+f"(c[3])
        : "r"(a[0]), "r"(a[1]), "r"(a[2]), "r"(a[3]), "r"(b0), "r"(b1));
}

__device__ __forceinline__ void cpa16(uint32_t dst, const void* src) {
    asm volatile("cp.async.cg.shared.global [%0], [%1], 16;"
                 :: "r"(dst), "l"(src) : "memory");
}

// ---------------- pre-pass: x -> transposed fp16 plane ----------------
__global__ void prep_x(const float* __restrict__ x) {
    int id = blockIdx.x * blockDim.x + threadIdx.x;   // 0 .. 64*16384-1
    int d = id >> 14;
    int j = id & (NN - 1);
    g_xT[(size_t)d * NN + j] = __float2half(x[(size_t)j * DIMF + d]);
}

// ---------------- main fused convert + mma.sync GEMM ----------------
__global__ void __launch_bounds__(THREADS, 2)
gp_mma(const float* __restrict__ x, const int* __restrict__ adj,
       float* __restrict__ out) {
    extern __shared__ __align__(1024) char smem[];
    const uint32_t sb = smem_u32(smem);
    const int tid = threadIdx.x;
    const int lane = tid & 31;
    const int wid = tid >> 5;          // 0..3
    const int wm = wid >> 1;           // 0..1 : 32-row slice
    const int wk = wid & 1;            // 0..1 : k-half of each chunk

    // balanced row range (55/56 real rows inside a 64-row tile)
    const int r_lo = (int)(((long long)blockIdx.x * NN) / GRIDX);
    const int r_hi = (int)(((long long)(blockIdx.x + 1) * NN) / GRIDX);
    const int cnt = r_hi - r_lo;

    const uint32_t wb = sb + (uint32_t)wid * W_BYTES;   // this warp's ring

    // ---- producer A: warp-private quadrant (32 rows x 128B), coalesced ----
    // lane -> row (lane>>3)+4i, granule (lane&7); swizzle g^=(row&3)<<1
    const int* aps = adj + (size_t)(r_lo + wm * 32 + (lane >> 3)) * NN +
                     wk * 32 + (lane & 7) * 4;
    uint32_t adst[8];
    bool amask[8];
#pragma unroll
    for (int i = 0; i < 8; i++) {
        uint32_t lr = (uint32_t)((lane >> 3) + 4 * i);
        adst[i] = lr * 128 + ((((uint32_t)lane & 7u) ^ ((lr & 3u) << 1)) << 4);
        amask[i] = (int)(wm * 32 + lr) < cnt;
    }

    // ---- producer B: warp-private k-half (64 n-rows x 64B), layout [g][n] ----
    // lane -> n (lane>>2)+8i, granule (lane&3); dst = 4096 + g*1024 + n*16
    const __half* bps = g_xT + (size_t)(lane >> 2) * NN + wk * 32 + (lane & 3) * 8;
    uint32_t bdst[8];
#pragma unroll
    for (int i = 0; i < 8; i++)
        bdst[i] = 4096 + ((uint32_t)lane & 3u) * 1024 +
                  (uint32_t)((lane >> 2) + 8 * i) * 16;

    // ---- consumer addressing ----
    const uint32_t xr = (((uint32_t)lane >> 2) & 3u) << 2;
    uint32_t rowb[4];   // [mt*2 + jl] -> local quadrant row * 128
#pragma unroll
    for (int mt = 0; mt < 2; mt++)
#pragma unroll
        for (int jl = 0; jl < 2; jl++)
            rowb[mt * 2 + jl] =
                (uint32_t)(mt * 16 + (lane >> 2) + jl * 8) * 128;
    uint32_t kuo[4];    // [ktl*2 + jh] -> swizzled 8B-unit offset (16 units/row)
#pragma unroll
    for (int ktl = 0; ktl < 2; ktl++)
#pragma unroll
        for (int jh = 0; jh < 2; jh++)
            kuo[ktl * 2 + jh] =
                (((uint32_t)(ktl * 8 + (lane & 3) + jh * 4) ^ xr) << 3);

    // B ldmatrix: addr = 4096 + (ktl*2 + kseg)*1024 + n*16 (no swizzle needed)
    uint32_t bfix[4];
#pragma unroll
    for (int p = 0; p < 4; p++)
        bfix[p] = 4096 + ((((uint32_t)lane >> 3) & 1u) << 10) +
                  ((uint32_t)(p * 16 + (lane & 7) + ((lane >> 4) & 1) * 8) << 4);

    // ---- prologue: chunks 0,1 in flight (per-warp groups) ----
#pragma unroll
    for (int pre = 0; pre < 2; pre++) {
        const uint32_t st = wb + (uint32_t)pre * W_STAGE;
#pragma unroll
        for (int i = 0; i < 8; i++)
            if (amask[i])
                cpa16(st + adst[i], aps + (size_t)i * (4 * NN) + pre * KC);
#pragma unroll
        for (int i = 0; i < 8; i++)
            cpa16(st + bdst[i], bps + (size_t)i * (8 * NN) + pre * KC);
        asm volatile("cp.async.commit_group;" ::: "memory");
    }

    float acc[64];
#pragma unroll
    for (int i = 0; i < 64; i++) acc[i] = 0.f;

    int sr = 0, sw = 2;
    for (int c = 0; c < NC; c++) {
        // own groups: <=1 pending -> chunk c complete (per-thread state)
        asm volatile("cp.async.wait_group 1;" ::: "memory");
        __syncwarp();   // cross-lane visibility of this warp's stage data

        // issue chunk c+2 into stage sw (last read by THIS warp at iter c-1)
        if (c + 2 < NC) {
            const uint32_t st = wb + (uint32_t)sw * W_STAGE;
#pragma unroll
            for (int i = 0; i < 8; i++)
                if (amask[i])
                    cpa16(st + adst[i], aps + (size_t)i * (4 * NN) + (c + 2) * KC);
#pragma unroll
            for (int i = 0; i < 8; i++)
                cpa16(st + bdst[i], bps + (size_t)i * (8 * NN) + (c + 2) * KC);
        }
        asm volatile("cp.async.commit_group;" ::: "memory");

        const uint32_t st = wb + (uint32_t)sr * W_STAGE;

        // ---- compute chunk c: 2 k16 steps, 2 m-tiles x 8 n8-tiles ----
#pragma unroll
        for (int ktl = 0; ktl < 2; ktl++) {
            uint32_t b[4][4];
#pragma unroll
            for (int p = 0; p < 4; p++)
                ldmx4(b[p], st + bfix[p] + (uint32_t)ktl * 2048);
#pragma unroll
            for (int mt = 0; mt < 2; mt++) {
                uint32_t A[4];
#pragma unroll
                for (int j = 0; j < 4; j++) {
                    const uint2 v = *reinterpret_cast<const uint2*>(
                        smem + (st - sb) + rowb[mt * 2 + (j & 1)] +
                        kuo[ktl * 2 + (j >> 1)]);
                    A[j] = __byte_perm(v.x, v.y, 0x5410) * 0x3C00u;
                }
                float* am = acc + mt * 32;
#pragma unroll
                for (int p = 0; p < 4; p++) {
                    mma16816(am + p * 8 + 0, A, b[p][0], b[p][1]);
                    mma16816(am + p * 8 + 4, A, b[p][2], b[p][3]);
                }
            }
        }

        sr = (sr == STAGES - 1) ? 0 : sr + 1;
        sw = (sw == STAGES - 1) ? 0 : sw + 1;
    }

    // ---- cross-warp k-reduction via smem (one-time CTA barriers) ----
    __syncthreads();   // all warps done with their pipeline buffers
    if (wk == 1) {
#pragma unroll
        for (int q = 0; q < 16; q++)
            *reinterpret_cast<float4*>(smem + (uint32_t)wm * 8192 +
                                       (uint32_t)q * 512 + (uint32_t)lane * 16) =
                make_float4(acc[q * 4], acc[q * 4 + 1], acc[q * 4 + 2], acc[q * 4 + 3]);
    }
    __syncthreads();
    if (wk == 0) {
#pragma unroll
        for (int q = 0; q < 16; q++) {
            float4 v = *reinterpret_cast<const float4*>(
                smem + (uint32_t)wm * 8192 + (uint32_t)q * 512 + (uint32_t)lane * 16);
            acc[q * 4] += v.x;
            acc[q * 4 + 1] += v.y;
            acc[q * 4 + 2] += v.z;
            acc[q * 4 + 3] += v.w;
        }

        // ---- epilogue: out = acc + x (fp32 exact self term), masked rows ----
#pragma unroll
        for (int mt = 0; mt < 2; mt++) {
            const int rloc = wm * 32 + mt * 16 + (lane >> 2);
#pragma unroll
            for (int nt = 0; nt < 8; nt++) {
                const int col = nt * 8 + (lane & 3) * 2;
                const float* ap = acc + mt * 32 + nt * 4;
                if (rloc < cnt) {
                    const int r0 = r_lo + rloc;
                    float2 xv0 = *(const float2*)(x + (size_t)r0 * DIMF + col);
                    *(float2*)(out + (size_t)r0 * DIMF + col) =
                        make_float2(ap[0] + xv0.x, ap[1] + xv0.y);
                }
                if (rloc + 8 < cnt) {
                    const int r1 = r_lo + rloc + 8;
                    float2 xv1 = *(const float2*)(x + (size_t)r1 * DIMF + col);
                    *(float2*)(out + (size_t)r1 * DIMF + col) =
                        make_float2(ap[2] + xv1.x, ap[3] + xv1.y);
                }
            }
        }
    }
}

extern "C" void kernel_launch(void* const* d_in, const int* in_sizes, int n_in,
                              void* d_out, int out_size) {
    const float* x = (const float*)d_in[0];
    const int* adj = (const int*)d_in[1];
    float* out = (float*)d_out;

    prep_x<<<(NN * DIMF) / 256, 256>>>(x);

    cudaFuncSetAttribute(gp_mma, cudaFuncAttributeMaxDynamicSharedMemorySize,
                         DYN_SMEM);
    gp_mma<<<GRIDX, THREADS, DYN_SMEM>>>(x, adj, out);
}

// round 15
// speedup vs baseline: 2.6243x; 2.6243x over previous
#include <cuda_runtime.h>
#include <cuda_fp16.h>
#include <cstdint>

#define NN      16384
#define DIMF    64
#define GRIDX   296                   // 2 CTAs x 148 SMs, balanced
#define KC      64                    // K elements per pipeline chunk
#define NC      (NN / KC)             // 256 chunks
#define THREADS 128
#define A_STAGE 16384                 // raw int32 A tile: 64 rows x 256B
#define B_STAGE 8192                  // fp16 B tile: 64 rows x 128B
#define B_BASE  (4 * A_STAGE)         // 65536
#define DYN_SMEM (B_BASE + 4 * B_STAGE)   // 98304

// transposed x in fp16: g_xT[d][j] = (half)x[j][d]
__device__ __half g_xT[DIMF * NN];

// ---------------- helpers ----------------
__device__ __forceinline__ uint32_t smem_u32(const void* p) {
    uint32_t a;
    asm("{ .reg .u64 t; cvta.to.shared.u64 t, %1; cvt.u32.u64 %0, t; }"
        : "=r"(a) : "l"(p));
    return a;
}

__device__ __forceinline__ void ldmx4(uint32_t r[4], uint32_t addr) {
    asm volatile("ldmatrix.sync.aligned.m8n8.x4.shared.b16 {%0,%1,%2,%3}, [%4];"
                 : "=r"(r[0]), "=r"(r[1]), "=r"(r[2]), "=r"(r[3]) : "r"(addr));
}

__device__ __forceinline__ void mma16816(float* c, const uint32_t a[4],
                                         uint32_t b0, uint32_t b1) {
    asm volatile(
        "mma.sync.aligned.m16n8k16.row.col.f32.f16.f16.f32 "
        "{%0,%1,%2,%3}, {%4,%5,%6,%7}, {%8,%9}, {%0,%1,%2,%3};"
        : "+f"(c[0]), "+f"(c[1]), "+f"(c[2]), "+f"(c[3])
        : "r"(a[0]), "r"(a[1]), "r"(a[2]), "r"(a[3]), "r"(b0), "r"(b1));
}

__device__ __forceinline__ void cpa16(uint32_t dst, const void* src) {
    asm volatile("cp.async.cg.shared.global [%0], [%1], 16;"
                 :: "r"(dst), "l"(src) : "memory");
}

// ---------------- pre-pass: x -> transposed fp16 plane ----------------
__global__ void prep_x(const float* __restrict__ x) {
    int id = blockIdx.x * blockDim.x + threadIdx.x;   // 0 .. 64*16384-1
    int d = id >> 14;
    int j = id & (NN - 1);
    g_xT[(size_t)d * NN + j] = __float2half(x[(size_t)j * DIMF + d]);
}

// ---------------- main fused convert + mma.sync GEMM ----------------
__global__ void __launch_bounds__(THREADS, 2)
gp_mma(const float* __restrict__ x, const int* __restrict__ adj,
       float* __restrict__ out) {
    extern __shared__ __align__(1024) char smem[];
    const uint32_t sb = smem_u32(smem);
    const int tid = threadIdx.x;
    const int lane = tid & 31;
    const int wid = tid >> 5;          // 0..3

    // balanced row range (55/56 real rows inside a 64-row tile)
    const int r_lo = (int)(((long long)blockIdx.x * NN) / GRIDX);
    const int r_hi = (int)(((long long)(blockIdx.x + 1) * NN) / GRIDX);
    const int cnt = r_hi - r_lo;

    // ---- producer A: cp.async of RAW int32, coalesced, row-masked ----
    const int rowp = tid >> 4;          // 0..7
    const int gg = tid & 15;            // 16B granule of a 256B row
    const int* aps = adj + (size_t)(r_lo + rowp) * NN + gg * 4;
    uint32_t adst[8];
    bool amask[8];
#pragma unroll
    for (int i = 0; i < 8; i++) {
        uint32_t row = (uint32_t)(rowp + 8 * i);
        adst[i] = row * 256 + (((uint32_t)gg ^ ((row & 3u) << 1)) << 4);
        amask[i] = (int)row < cnt;
    }

    // ---- producer B: 2 threads/row, 64B (4 granules) each ----
    const int rowB = tid >> 1;          // 0..63
    const int hb = tid & 1;
    const __half* bptr = g_xT + (size_t)rowB * NN + hb * 32;
    uint32_t bsw[4];
    {
        uint32_t o0 = (uint32_t)rowB * 128 + (uint32_t)hb * 64;
#pragma unroll
        for (int i = 0; i < 4; i++) {
            uint32_t o = o0 + i * 16;
            bsw[i] = o ^ ((o >> 3) & 0x70);
        }
    }

    // ---- consumer addressing: warp = (wm rows-half, wk k-half) ----
    const int wm = wid >> 1;   // 0..1 : 32-row slice
    const int wk = wid & 1;    // 0..1 : k16 steps {wk*2, wk*2+1}
    const uint32_t xr = (((uint32_t)lane >> 2) & 3u) << 2;
    uint32_t rowb[4];   // [mt*2 + (j&1)] -> row*256
#pragma unroll
    for (int mt = 0; mt < 2; mt++)
#pragma unroll
        for (int jl = 0; jl < 2; jl++)
            rowb[mt * 2 + jl] =
                (uint32_t)(wm * 32 + mt * 16 + (lane >> 2) + jl * 8) * 256;
    uint32_t kuo[4];    // [ktl*2 + (j>>1)] -> swizzled unit byte offset
#pragma unroll
    for (int ktl = 0; ktl < 2; ktl++)
#pragma unroll
        for (int jh = 0; jh < 2; jh++)
            kuo[ktl * 2 + jh] =
                (((uint32_t)((wk * 2 + ktl) * 8 + (lane & 3) + jh * 4) ^ xr) << 3);

    // B: full 64 cols; 4 ldmatrix.x4 per k-step (swizzled, k advances by XOR)
    uint32_t bAddr[4];
#pragma unroll
    for (int p = 0; p < 4; p++) {
        uint32_t n = (uint32_t)(p * 16 + (lane & 7) + ((lane >> 4) & 1) * 8);
        uint32_t o = n * 128 + ((((uint32_t)lane >> 3) & 1) << 4);
        bAddr[p] = o ^ ((o >> 3) & 0x70);
    }

    // ---- prologue: chunks 0,1,2 in flight ----
#pragma unroll
    for (int pre = 0; pre < 3; pre++) {
        const uint32_t ad = sb + (uint32_t)pre * A_STAGE;
#pragma unroll
        for (int i = 0; i < 8; i++)
            if (amask[i])
                cpa16(ad + adst[i], aps + (size_t)i * (8 * NN) + pre * KC);
        const uint32_t bd = sb + B_BASE + (uint32_t)pre * B_STAGE;
#pragma unroll
        for (int i = 0; i < 4; i++)
            cpa16(bd + bsw[i], bptr + pre * KC + i * 8);
        asm volatile("cp.async.commit_group;" ::: "memory");
    }

    float acc[64];
#pragma unroll
    for (int i = 0; i < 64; i++) acc[i] = 0.f;

    for (int c = 0; c < NC; c++) {
        asm volatile("cp.async.wait_group 2;" ::: "memory");
        __syncthreads();   // group-c data visible; WAR for stage (c+3)&3

        if (c + 3 < NC) {
            const uint32_t ad = sb + (uint32_t)((c + 3) & 3) * A_STAGE;
#pragma unroll
            for (int i = 0; i < 8; i++)
                if (amask[i])
                    cpa16(ad + adst[i], aps + (size_t)i * (8 * NN) + (c + 3) * KC);
            const uint32_t bd = sb + B_BASE + (uint32_t)((c + 3) & 3) * B_STAGE;
#pragma unroll
            for (int i = 0; i < 4; i++)
                cpa16(bd + bsw[i], bptr + (size_t)(c + 3) * KC + i * 8);
        }
        asm volatile("cp.async.commit_group;" ::: "memory");

        const uint32_t aOff = (uint32_t)(c & 3) * A_STAGE;
        const uint32_t bBase = sb + B_BASE + (uint32_t)(c & 3) * B_STAGE;

        // ---- compute chunk c: this warp's 2 k16 steps, 2 m-tiles x 8 n-tiles ----
#pragma unroll
        for (int ktl = 0; ktl < 2; ktl++) {
            const uint32_t kx = (uint32_t)(wk * 2 + ktl) << 5;
            uint32_t b[4][4];
#pragma unroll
            for (int p = 0; p < 4; p++)
                ldmx4(b[p], bBase + (bAddr[p] ^ kx));
#pragma unroll
            for (int mt = 0; mt < 2; mt++) {
                uint32_t A[4];
#pragma unroll
                for (int j = 0; j < 4; j++) {
                    const uint2 v = *reinterpret_cast<const uint2*>(
                        smem + aOff + rowb[mt * 2 + (j & 1)] + kuo[ktl * 2 + (j >> 1)]);
                    A[j] = __byte_perm(v.x, v.y, 0x5410) * 0x3C00u;
                }
                float* am = acc + mt * 32;
#pragma unroll
                for (int p = 0; p < 4; p++) {
                    mma16816(am + p * 8 + 0, A, b[p][0], b[p][1]);
                    mma16816(am + p * 8 + 4, A, b[p][2], b[p][3]);
                }
            }
        }
    }

    // ---- cross-warp k-reduction via smem (reuses pipeline buffers) ----
    __syncthreads();   // all pipeline smem reads done
    if (wk == 1) {
#pragma unroll
        for (int q = 0; q < 16; q++)
            *reinterpret_cast<float4*>(smem + (uint32_t)wm * 8192 +
                                       (uint32_t)q * 512 + (uint32_t)lane * 16) =
                make_float4(acc[q * 4], acc[q * 4 + 1], acc[q * 4 + 2], acc[q * 4 + 3]);
    }
    __syncthreads();
    if (wk == 0) {
#pragma unroll
        for (int q = 0; q < 16; q++) {
            float4 v = *reinterpret_cast<const float4*>(
                smem + (uint32_t)wm * 8192 + (uint32_t)q * 512 + (uint32_t)lane * 16);
            acc[q * 4] += v.x;
            acc[q * 4 + 1] += v.y;
            acc[q * 4 + 2] += v.z;
            acc[q * 4 + 3] += v.w;
        }

        // ---- epilogue: out = acc + x (fp32 exact self term), masked rows ----
#pragma unroll
        for (int mt = 0; mt < 2; mt++) {
            const int rloc = wm * 32 + mt * 16 + (lane >> 2);
#pragma unroll
            for (int nt = 0; nt < 8; nt++) {
                const int col = nt * 8 + (lane & 3) * 2;
                const float* ap = acc + mt * 32 + nt * 4;
                if (rloc < cnt) {
                    const int r0 = r_lo + rloc;
                    float2 xv0 = *(const float2*)(x + (size_t)r0 * DIMF + col);
                    *(float2*)(out + (size_t)r0 * DIMF + col) =
                        make_float2(ap[0] + xv0.x, ap[1] + xv0.y);
                }
                if (rloc + 8 < cnt) {
                    const int r1 = r_lo + rloc + 8;
                    float2 xv1 = *(const float2*)(x + (size_t)r1 * DIMF + col);
                    *(float2*)(out + (size_t)r1 * DIMF + col) =
                        make_float2(ap[2] + xv1.x, ap[3] + xv1.y);
                }
            }
        }
    }
}

extern "C" void kernel_launch(void* const* d_in, const int* in_sizes, int n_in,
                              void* d_out, int out_size) {
    const float* x = (const float*)d_in[0];
    const int* adj = (const int*)d_in[1];
    float* out = (float*)d_out;

    prep_x<<<(NN * DIMF) / 256, 256>>>(x);

    cudaFuncSetAttribute(gp_mma, cudaFuncAttributeMaxDynamicSharedMemorySize,
                         DYN_SMEM);
    gp_mma<<<GRIDX, THREADS, DYN_SMEM>>>(x, adj, out);
}